// round 15
// baseline (speedup 1.0000x reference)
#include <cuda_runtime.h>
#include <cstdint>
#include <math.h>

// Problem constants
#define G  8
#define T  4096
#define H  1024
#define E  32
#define C  64
#define GT (G*T)                       // 32768 tokens
#define GTEC ((size_t)G*(size_t)T*(size_t)E*(size_t)C)   // 67,108,864

// GEMM: 128 tokens/block, 128 threads = 4 expert-groups x 32 token-quads
// Each thread: 8 experts x 4 adjacent tokens -> 16 FMA2 per 8 smem wavefronts.
#define MTILE 128
#define KTILE 32
#define NKC   (H/KTILE)                // 32
#define GEMM_BLOCKS (GT/MTILE)         // 256
#define GTHREADS 128
#define XW 132                         // xs row stride [k][tok]: 128 + 4 pad (16B-aligned)
#define WW 36                          // ws row stride [k][e]

#define NTHREADS 256
#define SEL_BLOCKS  (G*E)              // 256
#define ZERO_BLOCKS 2048

// Scratch (device globals; no allocations allowed)
__device__ float g_probs[G*E*T];       // probs transposed [g][e][t], 4 MB
__device__ float g_zpart[GEMM_BLOCKS];
__device__ float g_topv[G*E*C];
__device__ int   g_topt[G*E*C];

// ---------------------------------------------------------------------------
// Kernel A: expert-split GEMM, warp-uniform expert group, 4 tokens/thread.
// Per-scalar-logit accumulation order (kc asc, kk asc, f32x2 expert pairing)
// identical to R12/R14 -> bit-identical logits -> identical selection.
// ---------------------------------------------------------------------------
__global__ void __launch_bounds__(GTHREADS)
router_gemm(const float* __restrict__ x,   // [G,T,H]
            const float* __restrict__ Wm,  // [H,E]
            const float* __restrict__ bv)  // [E]
{
    const int bid = blockIdx.x;
    const int tid = threadIdx.x;
    const int eh  = tid >> 5;              // 0..3, uniform per warp
    const int tq  = tid & 31;              // token-quad (lane) 0..31

    __shared__ __align__(16) float xs[KTILE * XW];   // [k][tok], 32 x 132
    __shared__ __align__(16) float ws[KTILE * WW];   // [k][e]
    __shared__ float psm[MTILE * 33];                // logits/probs staging
    __shared__ float zsm[MTILE];

    const int gtBase = bid * MTILE;
    const int g   = gtBase >> 12;
    const int tt0 = gtBase & (T - 1);
    const float* xbase = x + (size_t)gtBase * H;

    // acc[4u + i]: token (4*tq+u), expert pair (eh*8 + 2i, +1)
    unsigned long long acc[16];
#pragma unroll
    for (int i = 0; i < 16; i++) acc[i] = 0ull;

    // prefetch: x = 8 float4/thread (128 tok x 8 f4), W = 2 float4/thread
    float4 pfx[8];
    float4 pfw[2];
#pragma unroll
    for (int r = 0; r < 8; r++) {
        int s  = r * GTHREADS + tid;       // [0,1024)
        int tl = s >> 3;
        int c  = s & 7;
        pfx[r] = *reinterpret_cast<const float4*>(xbase + (size_t)tl * H + c * 4);
    }
#pragma unroll
    for (int r = 0; r < 2; r++)
        pfw[r] = *reinterpret_cast<const float4*>(Wm + (r * GTHREADS + tid) * 4);

    for (int kc = 0; kc < NKC; kc++) {
        __syncthreads();                 // previous compute done
        // transpose-store x into [k][tok]
#pragma unroll
        for (int r = 0; r < 8; r++) {
            int s  = r * GTHREADS + tid;
            int tl = s >> 3;
            int c  = s & 7;
            xs[(4*c + 0) * XW + tl] = pfx[r].x;
            xs[(4*c + 1) * XW + tl] = pfx[r].y;
            xs[(4*c + 2) * XW + tl] = pfx[r].z;
            xs[(4*c + 3) * XW + tl] = pfx[r].w;
        }
#pragma unroll
        for (int r = 0; r < 2; r++) {
            int i = r * GTHREADS + tid;    // [0,256): k = i>>3, e4 = i&7
            *reinterpret_cast<float4*>(ws + (i >> 3) * WW + (i & 7) * 4) = pfw[r];
        }
        __syncthreads();

        if (kc + 1 < NKC) {
            const float* xn = xbase + (kc + 1) * KTILE;
#pragma unroll
            for (int r = 0; r < 8; r++) {
                int s  = r * GTHREADS + tid;
                int tl = s >> 3;
                int c  = s & 7;
                pfx[r] = *reinterpret_cast<const float4*>(xn + (size_t)tl * H + c * 4);
            }
            const float* wn = Wm + (kc + 1) * KTILE * E;
#pragma unroll
            for (int r = 0; r < 2; r++)
                pfw[r] = *reinterpret_cast<const float4*>(wn + (r * GTHREADS + tid) * 4);
        }

#pragma unroll
        for (int kk = 0; kk < KTILE; kk++) {
            // x quad: LDS.128, lane l reads bytes [16l,16l+16) -> conflict-free
            const float4 xv =
                *reinterpret_cast<const float4*>(xs + kk * XW + 4 * tq);
            unsigned long long xx0, xx1, xx2, xx3;
            asm("mov.b64 %0, {%1,%1};" : "=l"(xx0) : "r"(__float_as_uint(xv.x)));
            asm("mov.b64 %0, {%1,%1};" : "=l"(xx1) : "r"(__float_as_uint(xv.y)));
            asm("mov.b64 %0, {%1,%1};" : "=l"(xx2) : "r"(__float_as_uint(xv.z)));
            asm("mov.b64 %0, {%1,%1};" : "=l"(xx3) : "r"(__float_as_uint(xv.w)));
            const ulonglong2* wr =
                reinterpret_cast<const ulonglong2*>(ws + kk * WW + (eh << 3));
            ulonglong2 w0 = wr[0];   // broadcast: warp-uniform address
            ulonglong2 w1 = wr[1];
            asm("fma.rn.f32x2 %0, %1, %2, %0;" : "+l"(acc[0])  : "l"(xx0), "l"(w0.x));
            asm("fma.rn.f32x2 %0, %1, %2, %0;" : "+l"(acc[1])  : "l"(xx0), "l"(w0.y));
            asm("fma.rn.f32x2 %0, %1, %2, %0;" : "+l"(acc[2])  : "l"(xx0), "l"(w1.x));
            asm("fma.rn.f32x2 %0, %1, %2, %0;" : "+l"(acc[3])  : "l"(xx0), "l"(w1.y));
            asm("fma.rn.f32x2 %0, %1, %2, %0;" : "+l"(acc[4])  : "l"(xx1), "l"(w0.x));
            asm("fma.rn.f32x2 %0, %1, %2, %0;" : "+l"(acc[5])  : "l"(xx1), "l"(w0.y));
            asm("fma.rn.f32x2 %0, %1, %2, %0;" : "+l"(acc[6])  : "l"(xx1), "l"(w1.x));
            asm("fma.rn.f32x2 %0, %1, %2, %0;" : "+l"(acc[7])  : "l"(xx1), "l"(w1.y));
            asm("fma.rn.f32x2 %0, %1, %2, %0;" : "+l"(acc[8])  : "l"(xx2), "l"(w0.x));
            asm("fma.rn.f32x2 %0, %1, %2, %0;" : "+l"(acc[9])  : "l"(xx2), "l"(w0.y));
            asm("fma.rn.f32x2 %0, %1, %2, %0;" : "+l"(acc[10]) : "l"(xx2), "l"(w1.x));
            asm("fma.rn.f32x2 %0, %1, %2, %0;" : "+l"(acc[11]) : "l"(xx2), "l"(w1.y));
            asm("fma.rn.f32x2 %0, %1, %2, %0;" : "+l"(acc[12]) : "l"(xx3), "l"(w0.x));
            asm("fma.rn.f32x2 %0, %1, %2, %0;" : "+l"(acc[13]) : "l"(xx3), "l"(w0.y));
            asm("fma.rn.f32x2 %0, %1, %2, %0;" : "+l"(acc[14]) : "l"(xx3), "l"(w1.x));
            asm("fma.rn.f32x2 %0, %1, %2, %0;" : "+l"(acc[15]) : "l"(xx3), "l"(w1.y));
        }
    }

    // ---- gather raw logits to smem (bit-exact values) ----
#pragma unroll
    for (int u = 0; u < 4; u++) {
        const int tk = 4 * tq + u;
#pragma unroll
        for (int i = 0; i < 4; i++) {
            float2 f = *reinterpret_cast<float2*>(&acc[4*u + i]);
            psm[tk * 33 + (eh << 3) + 2*i]     = f.x;
            psm[tk * 33 + (eh << 3) + 2*i + 1] = f.y;
        }
    }
    __syncthreads();

    // ---- eh==0 threads: exact R5/R12 softmax sequence, 4 tokens each ----
    if (eh == 0) {
#pragma unroll
        for (int u = 0; u < 4; u++) {
            const int tk = 4 * tq + u;
            float l[E];
#pragma unroll
            for (int e = 0; e < E; e++) l[e] = psm[tk * 33 + e];
#pragma unroll
            for (int e = 0; e < E; e++) l[e] += __ldg(&bv[e]);

            float m = l[0];
#pragma unroll
            for (int e = 1; e < E; e++) m = fmaxf(m, l[e]);
            float s = 0.f;
#pragma unroll
            for (int e = 0; e < E; e++) { l[e] = expf(l[e] - m); s += l[e]; }
            const float inv = 1.f / s;
#pragma unroll
            for (int e = 0; e < E; e++) psm[tk * 33 + e] = l[e] * inv;

            const float lse = m + logf(s);
            zsm[tk] = lse * lse;
        }
    }
    __syncthreads();

    // ---- coalesced transposed prob write: [e][t] runs of 128 ----
#pragma unroll
    for (int r = 0; r < 32; r++) {
        int idx = r * GTHREADS + tid;          // [0, 4096)
        int e = idx >> 7;
        int t = idx & (MTILE - 1);
        g_probs[(size_t)(g * E + e) * T + tt0 + t] = psm[t * 33 + e];
    }

    if (tid == 0) {
        float s = 0.f;
#pragma unroll
        for (int i = 0; i < MTILE; i++) s += zsm[i];
        g_zpart[bid] = s;
    }
}

// ---------------------------------------------------------------------------
// Kernel B: blocks [0,256) = top-64 selection per (g,e) -> compact g_top
//           blocks [256, 2304) = grid-stride streaming zero fill of out.
// ---------------------------------------------------------------------------
__global__ __launch_bounds__(NTHREADS)
void router_zero_sel(float* __restrict__ out)
{
    const int bid = blockIdx.x;
    const int tid = threadIdx.x;

    if (bid >= SEL_BLOCKS) {
        uint4 z; z.x = 0u; z.y = 0u; z.z = 0u; z.w = 0u;
        uint4* o4 = reinterpret_cast<uint4*>(out);
        const size_t n4 = (2*GTEC) / 4;                    // 33,554,432
        size_t i = (size_t)(bid - SEL_BLOCKS) * NTHREADS + tid;
        const size_t stride = (size_t)ZERO_BLOCKS * NTHREADS;
        for (; i < n4; i += stride) __stcs(o4 + i, z);
        return;
    }

    const float* row = g_probs + (size_t)bid * T;

    float v[16];
#pragma unroll
    for (int j = 0; j < 16; j++) v[j] = row[tid + j * NTHREADS];

    float bvv = -INFINITY; int bt = tid;
#pragma unroll
    for (int j = 0; j < 16; j++)
        if (v[j] > bvv) { bvv = v[j]; bt = j * NTHREADS + tid; }

    __shared__ float swv[8];
    __shared__ int   swt[8];
    __shared__ int   wint;

    const int lane = tid & 31;
    const int wrp  = tid >> 5;

    for (int c = 0; c < C; c++) {
        float rv = bvv; int rt = bt;
#pragma unroll
        for (int off = 16; off; off >>= 1) {
            float ov = __shfl_xor_sync(0xffffffffu, rv, off);
            int   oi = __shfl_xor_sync(0xffffffffu, rt, off);
            if (ov > rv || (ov == rv && oi < rt)) { rv = ov; rt = oi; }
        }
        if (lane == 0) { swv[wrp] = rv; swt[wrp] = rt; }
        __syncthreads();
        if (tid == 0) {
            float Rv = swv[0]; int Rt = swt[0];
#pragma unroll
            for (int w = 1; w < 8; w++)
                if (swv[w] > Rv || (swv[w] == Rv && swt[w] < Rt)) {
                    Rv = swv[w]; Rt = swt[w];
                }
            wint = Rt;
            g_topv[bid * C + c] = Rv;
            g_topt[bid * C + c] = Rt;
        }
        __syncthreads();
        const int wt = wint;
        if ((wt & (NTHREADS - 1)) == tid) {
            v[wt >> 8] = -INFINITY;
            bvv = -INFINITY; bt = tid;
#pragma unroll
            for (int j = 0; j < 16; j++)
                if (v[j] > bvv) { bvv = v[j]; bt = j * NTHREADS + tid; }
        }
    }
}

// ---------------------------------------------------------------------------
// Kernel C: scatter the 16384 winners + z-loss finalize.
// ---------------------------------------------------------------------------
__global__ __launch_bounds__(NTHREADS)
void router_scatter(float* __restrict__ out)
{
    const int idx = blockIdx.x * NTHREADS + threadIdx.x;   // [0, 16384)

    if (idx == 0) {
        float s = 0.f;
        for (int i = 0; i < GEMM_BLOCKS; i++) s += g_zpart[i];
        out[2 * GTEC] = s / (float)GT;
    }

    const int ge = idx >> 6;
    const int c  = idx & (C - 1);
    const int g  = ge >> 5;
    const int e  = ge & (E - 1);
    const int t  = g_topt[idx];
    const float val = g_topv[idx];

    const size_t off = (((size_t)(g * T + t)) * E + e) * C + c;
    out[off]        = val;            // combine
    out[GTEC + off] = 1.0f;           // dispatch
}

// ---------------------------------------------------------------------------
extern "C" void kernel_launch(void* const* d_in, const int* in_sizes, int n_in,
                              void* d_out, int out_size)
{
    const float* x  = (const float*)d_in[0];
    const float* Wm = (const float*)d_in[1];
    const float* bv = (const float*)d_in[2];
    float* out = (float*)d_out;

    // 3 launches/call: ncu idx-5 capture = router_gemm of the 2nd replay
    router_gemm<<<GEMM_BLOCKS, GTHREADS>>>(x, Wm, bv);
    router_zero_sel<<<SEL_BLOCKS + ZERO_BLOCKS, NTHREADS>>>(out);
    router_scatter<<<(G * E * C) / NTHREADS, NTHREADS>>>(out);
}

// round 16
// speedup vs baseline: 1.0306x; 1.0306x over previous
#include <cuda_runtime.h>
#include <cstdint>
#include <math.h>

// Problem constants
#define G  8
#define T  4096
#define H  1024
#define E  32
#define C  64
#define GT (G*T)                       // 32768 tokens
#define GTEC ((size_t)G*(size_t)T*(size_t)E*(size_t)C)   // 67,108,864

// GEMM (R14, best measured 77.0us): 128 tokens/block, 256 threads, KTILE=64
#define MTILE 128
#define KTILE 64
#define NKC   (H/KTILE)                // 16
#define GEMM_BLOCKS (GT/MTILE)         // 256
#define GTHREADS 256
#define XW 130                         // xs row stride [k][tok]
#define WW 36                          // ws row stride [k][e]

#define NTHREADS 256
#define SEL_BLOCKS  (G*E)              // 256
#define ZERO_BLOCKS 2048

// Scratch (device globals; no allocations allowed)
__device__ float g_probs[G*E*T];       // probs transposed [g][e][t], 4 MB
__device__ float g_zpart[GEMM_BLOCKS];
__device__ unsigned int g_done;        // memset completion counter

// ---------------------------------------------------------------------------
// Kernel A: expert-split GEMM (R14). Bit-identical logits to R12/R14.
// Also resets g_done for this replay (runs before zero_sel on the stream).
// ---------------------------------------------------------------------------
__global__ void __launch_bounds__(GTHREADS)
router_gemm(const float* __restrict__ x,   // [G,T,H]
            const float* __restrict__ Wm,  // [H,E]
            const float* __restrict__ bv)  // [E]
{
    const int bid = blockIdx.x;
    const int tid = threadIdx.x;
    const int eh  = tid >> 6;              // 0..3, uniform per warp
    const int tl2 = tid & 63;              // token-pair index 0..63

    if (bid == 0 && tid == 0) g_done = 0u;   // reset for this replay

    __shared__ __align__(16) float xs[KTILE * XW];   // 64 x 130
    __shared__ __align__(16) float ws[KTILE * WW];   // 64 x 36
    float* psm = xs;                       // overlay (dead after mainloop)
    float* zsm = ws;

    const int gtBase = bid * MTILE;
    const int g   = gtBase >> 12;
    const int tt0 = gtBase & (T - 1);
    const float* xbase = x + (size_t)gtBase * H;

    unsigned long long acc[8];
#pragma unroll
    for (int i = 0; i < 8; i++) acc[i] = 0ull;

    float4 pfx[8];
    float4 pfw[2];
#pragma unroll
    for (int r = 0; r < 8; r++) {
        int h  = r >> 2;
        int s2 = (r & 3) * GTHREADS + tid;
        int tl = s2 >> 3;
        int c  = s2 & 7;
        pfx[r] = *reinterpret_cast<const float4*>(
            xbase + (size_t)tl * H + 32 * h + c * 4);
    }
#pragma unroll
    for (int r = 0; r < 2; r++)
        pfw[r] = *reinterpret_cast<const float4*>(Wm + (r * GTHREADS + tid) * 4);

    for (int kc = 0; kc < NKC; kc++) {
        __syncthreads();
#pragma unroll
        for (int r = 0; r < 8; r++) {
            int h  = r >> 2;
            int s2 = (r & 3) * GTHREADS + tid;
            int tl = s2 >> 3;
            int c  = s2 & 7;
            int k0 = 32 * h + 4 * c;
            xs[(k0 + 0) * XW + tl] = pfx[r].x;
            xs[(k0 + 1) * XW + tl] = pfx[r].y;
            xs[(k0 + 2) * XW + tl] = pfx[r].z;
            xs[(k0 + 3) * XW + tl] = pfx[r].w;
        }
#pragma unroll
        for (int r = 0; r < 2; r++) {
            int i = r * GTHREADS + tid;
            *reinterpret_cast<float4*>(ws + (i >> 3) * WW + (i & 7) * 4) = pfw[r];
        }
        __syncthreads();

        if (kc + 1 < NKC) {
            const float* xn = xbase + (kc + 1) * KTILE;
#pragma unroll
            for (int r = 0; r < 8; r++) {
                int h  = r >> 2;
                int s2 = (r & 3) * GTHREADS + tid;
                int tl = s2 >> 3;
                int c  = s2 & 7;
                pfx[r] = *reinterpret_cast<const float4*>(
                    xn + (size_t)tl * H + 32 * h + c * 4);
            }
            const float* wn = Wm + (kc + 1) * KTILE * E;
#pragma unroll
            for (int r = 0; r < 2; r++)
                pfw[r] = *reinterpret_cast<const float4*>(wn + (r * GTHREADS + tid) * 4);
        }

#pragma unroll
        for (int kk = 0; kk < KTILE; kk++) {
            const float2 xv =
                *reinterpret_cast<const float2*>(xs + kk * XW + 2 * tl2);
            unsigned long long xx0, xx1;
            asm("mov.b64 %0, {%1,%1};" : "=l"(xx0) : "r"(__float_as_uint(xv.x)));
            asm("mov.b64 %0, {%1,%1};" : "=l"(xx1) : "r"(__float_as_uint(xv.y)));
            const ulonglong2* wr =
                reinterpret_cast<const ulonglong2*>(ws + kk * WW + (eh << 3));
            ulonglong2 w0 = wr[0];   // broadcast: warp-uniform address
            ulonglong2 w1 = wr[1];
            asm("fma.rn.f32x2 %0, %1, %2, %0;" : "+l"(acc[0]) : "l"(xx0), "l"(w0.x));
            asm("fma.rn.f32x2 %0, %1, %2, %0;" : "+l"(acc[1]) : "l"(xx0), "l"(w0.y));
            asm("fma.rn.f32x2 %0, %1, %2, %0;" : "+l"(acc[2]) : "l"(xx0), "l"(w1.x));
            asm("fma.rn.f32x2 %0, %1, %2, %0;" : "+l"(acc[3]) : "l"(xx0), "l"(w1.y));
            asm("fma.rn.f32x2 %0, %1, %2, %0;" : "+l"(acc[4]) : "l"(xx1), "l"(w0.x));
            asm("fma.rn.f32x2 %0, %1, %2, %0;" : "+l"(acc[5]) : "l"(xx1), "l"(w0.y));
            asm("fma.rn.f32x2 %0, %1, %2, %0;" : "+l"(acc[6]) : "l"(xx1), "l"(w1.x));
            asm("fma.rn.f32x2 %0, %1, %2, %0;" : "+l"(acc[7]) : "l"(xx1), "l"(w1.y));
        }
    }

    __syncthreads();   // xs/ws dead; psm/zsm overlay

    {
        const int t0 = 2 * tl2, t1 = 2 * tl2 + 1;
#pragma unroll
        for (int i = 0; i < 4; i++) {
            float2 f0 = *reinterpret_cast<float2*>(&acc[i]);
            float2 f1 = *reinterpret_cast<float2*>(&acc[4 + i]);
            psm[t0 * 33 + (eh << 3) + 2*i]     = f0.x;
            psm[t0 * 33 + (eh << 3) + 2*i + 1] = f0.y;
            psm[t1 * 33 + (eh << 3) + 2*i]     = f1.x;
            psm[t1 * 33 + (eh << 3) + 2*i + 1] = f1.y;
        }
    }
    __syncthreads();

    if (eh == 0) {
#pragma unroll
        for (int u = 0; u < 2; u++) {
            const int tk = 2 * tl2 + u;
            float l[E];
#pragma unroll
            for (int e = 0; e < E; e++) l[e] = psm[tk * 33 + e];
#pragma unroll
            for (int e = 0; e < E; e++) l[e] += __ldg(&bv[e]);

            float m = l[0];
#pragma unroll
            for (int e = 1; e < E; e++) m = fmaxf(m, l[e]);
            float s = 0.f;
#pragma unroll
            for (int e = 0; e < E; e++) { l[e] = expf(l[e] - m); s += l[e]; }
            const float inv = 1.f / s;
#pragma unroll
            for (int e = 0; e < E; e++) psm[tk * 33 + e] = l[e] * inv;

            const float lse = m + logf(s);
            zsm[tk] = lse * lse;
        }
    }
    __syncthreads();

#pragma unroll
    for (int r = 0; r < 16; r++) {
        int idx = r * GTHREADS + tid;
        int e = idx >> 7;
        int t = idx & (MTILE - 1);
        g_probs[(size_t)(g * E + e) * T + tt0 + t] = psm[t * 33 + e];
    }

    if (tid == 0) {
        float s = 0.f;
#pragma unroll
        for (int i = 0; i < MTILE; i++) s += zsm[i];
        g_zpart[bid] = s;
    }
}

// ---------------------------------------------------------------------------
// Kernel B: bid<256 = top-64 selection (winners in smem), then wait for the
//           memset counter and scatter directly + z-loss (block 0).
//           bid>=256 = grid-stride streaming zero fill, then signal counter.
// ---------------------------------------------------------------------------
__global__ __launch_bounds__(NTHREADS)
void router_zero_sel(float* __restrict__ out)
{
    const int bid = blockIdx.x;
    const int tid = threadIdx.x;

    if (bid >= SEL_BLOCKS) {
        uint4 z; z.x = 0u; z.y = 0u; z.z = 0u; z.w = 0u;
        uint4* o4 = reinterpret_cast<uint4*>(out);
        const size_t n4 = (2*GTEC) / 4;                    // 33,554,432
        size_t i = (size_t)(bid - SEL_BLOCKS) * NTHREADS + tid;
        const size_t stride = (size_t)ZERO_BLOCKS * NTHREADS;
        for (; i < n4; i += stride) __stcs(o4 + i, z);
        __threadfence();               // release: zeros visible before signal
        __syncthreads();
        if (tid == 0) atomicAdd(&g_done, 1u);
        return;
    }

    // ---- selection for (g,e) = bid ----
    const int g = bid >> 5;
    const int e = bid & (E - 1);
    const float* row = g_probs + (size_t)bid * T;

    float v[16];
#pragma unroll
    for (int j = 0; j < 16; j++) v[j] = row[tid + j * NTHREADS];

    float bvv = -INFINITY; int bt = tid;
#pragma unroll
    for (int j = 0; j < 16; j++)
        if (v[j] > bvv) { bvv = v[j]; bt = j * NTHREADS + tid; }

    __shared__ float swv[8];
    __shared__ int   swt[8];
    __shared__ int   wint;
    __shared__ float topv_sh[C];
    __shared__ int   topt_sh[C];

    const int lane = tid & 31;
    const int wrp  = tid >> 5;

    for (int c = 0; c < C; c++) {
        float rv = bvv; int rt = bt;
#pragma unroll
        for (int off = 16; off; off >>= 1) {
            float ov = __shfl_xor_sync(0xffffffffu, rv, off);
            int   oi = __shfl_xor_sync(0xffffffffu, rt, off);
            if (ov > rv || (ov == rv && oi < rt)) { rv = ov; rt = oi; }
        }
        if (lane == 0) { swv[wrp] = rv; swt[wrp] = rt; }
        __syncthreads();
        if (tid == 0) {
            float Rv = swv[0]; int Rt = swt[0];
#pragma unroll
            for (int w = 1; w < 8; w++)
                if (swv[w] > Rv || (swv[w] == Rv && swt[w] < Rt)) {
                    Rv = swv[w]; Rt = swt[w];
                }
            wint = Rt;
            topv_sh[c] = Rv;
            topt_sh[c] = Rt;
        }
        __syncthreads();
        const int wt = wint;
        if ((wt & (NTHREADS - 1)) == tid) {
            v[wt >> 8] = -INFINITY;
            bvv = -INFINITY; bt = tid;
#pragma unroll
            for (int j = 0; j < 16; j++)
                if (v[j] > bvv) { bvv = v[j]; bt = j * NTHREADS + tid; }
        }
    }

    // ---- wait for ALL memset blocks, then scatter this row's winners ----
    if (tid == 0) {
        volatile unsigned int* p = &g_done;
        while (*p < ZERO_BLOCKS) __nanosleep(256);
    }
    __syncthreads();
    __threadfence();   // acquire: zeros ordered before our scatter writes

    if (tid < C) {
        const int   t   = topt_sh[tid];
        const float val = topv_sh[tid];
        const size_t off = (((size_t)(g * T + t)) * E + e) * C + tid;
        out[off]        = val;            // combine
        out[GTEC + off] = 1.0f;           // dispatch
    }

    if (bid == 0 && tid == 0) {           // z-loss finalize
        float s = 0.f;
        for (int i = 0; i < GEMM_BLOCKS; i++) s += g_zpart[i];
        out[2 * GTEC] = s / (float)GT;
    }
}

// ---------------------------------------------------------------------------
extern "C" void kernel_launch(void* const* d_in, const int* in_sizes, int n_in,
                              void* d_out, int out_size)
{
    const float* x  = (const float*)d_in[0];
    const float* Wm = (const float*)d_in[1];
    const float* bv = (const float*)d_in[2];
    float* out = (float*)d_out;

    router_gemm<<<GEMM_BLOCKS, GTHREADS>>>(x, Wm, bv);
    router_zero_sel<<<SEL_BLOCKS + ZERO_BLOCKS, NTHREADS>>>(out);
}

// round 17
// speedup vs baseline: 1.0423x; 1.0114x over previous
#include <cuda_runtime.h>
#include <cstdint>
#include <math.h>

// Problem constants
#define G  8
#define T  4096
#define H  1024
#define E  32
#define C  64
#define GT (G*T)                       // 32768 tokens
#define GTEC ((size_t)G*(size_t)T*(size_t)E*(size_t)C)   // 67,108,864

// GEMM (R14/R16, measured 77.0us): 128 tokens/block, 256 threads, KTILE=64
#define MTILE 128
#define KTILE 64
#define NKC   (H/KTILE)                // 16
#define GEMM_BLOCKS (GT/MTILE)         // 256
#define GTHREADS 256
#define XW 130                         // xs row stride [k][tok]
#define WW 36                          // ws row stride [k][e]

#define NTHREADS 256
#define SEL_BLOCKS  (G*E)              // 256
#define ZERO_BLOCKS 2048
#define N4H (GTEC/4)                   // uint4 per half = 16,777,216

// Scratch (device globals; no allocations allowed)
__device__ float g_probs[G*E*T];       // probs transposed [g][e][t], 4 MB
__device__ float g_zpart[GEMM_BLOCKS];
__device__ unsigned int g_done_c;      // combine-half memset completion
__device__ unsigned int g_done_d;      // dispatch-half memset completion

// ---------------------------------------------------------------------------
// Kernel A: expert-split GEMM (R14/R16, bit-identical logits).
// Resets both memset counters for this replay (stream-ordered before k2).
// ---------------------------------------------------------------------------
__global__ void __launch_bounds__(GTHREADS)
router_gemm(const float* __restrict__ x,   // [G,T,H]
            const float* __restrict__ Wm,  // [H,E]
            const float* __restrict__ bv)  // [E]
{
    const int bid = blockIdx.x;
    const int tid = threadIdx.x;
    const int eh  = tid >> 6;              // 0..3, uniform per warp
    const int tl2 = tid & 63;              // token-pair index 0..63

    if (bid == 0 && tid == 0) { g_done_c = 0u; g_done_d = 0u; }

    __shared__ __align__(16) float xs[KTILE * XW];   // 64 x 130
    __shared__ __align__(16) float ws[KTILE * WW];   // 64 x 36
    float* psm = xs;                       // overlay (dead after mainloop)
    float* zsm = ws;

    const int gtBase = bid * MTILE;
    const int g   = gtBase >> 12;
    const int tt0 = gtBase & (T - 1);
    const float* xbase = x + (size_t)gtBase * H;

    unsigned long long acc[8];
#pragma unroll
    for (int i = 0; i < 8; i++) acc[i] = 0ull;

    float4 pfx[8];
    float4 pfw[2];
#pragma unroll
    for (int r = 0; r < 8; r++) {
        int h  = r >> 2;
        int s2 = (r & 3) * GTHREADS + tid;
        int tl = s2 >> 3;
        int c  = s2 & 7;
        pfx[r] = *reinterpret_cast<const float4*>(
            xbase + (size_t)tl * H + 32 * h + c * 4);
    }
#pragma unroll
    for (int r = 0; r < 2; r++)
        pfw[r] = *reinterpret_cast<const float4*>(Wm + (r * GTHREADS + tid) * 4);

    for (int kc = 0; kc < NKC; kc++) {
        __syncthreads();
#pragma unroll
        for (int r = 0; r < 8; r++) {
            int h  = r >> 2;
            int s2 = (r & 3) * GTHREADS + tid;
            int tl = s2 >> 3;
            int c  = s2 & 7;
            int k0 = 32 * h + 4 * c;
            xs[(k0 + 0) * XW + tl] = pfx[r].x;
            xs[(k0 + 1) * XW + tl] = pfx[r].y;
            xs[(k0 + 2) * XW + tl] = pfx[r].z;
            xs[(k0 + 3) * XW + tl] = pfx[r].w;
        }
#pragma unroll
        for (int r = 0; r < 2; r++) {
            int i = r * GTHREADS + tid;
            *reinterpret_cast<float4*>(ws + (i >> 3) * WW + (i & 7) * 4) = pfw[r];
        }
        __syncthreads();

        if (kc + 1 < NKC) {
            const float* xn = xbase + (kc + 1) * KTILE;
#pragma unroll
            for (int r = 0; r < 8; r++) {
                int h  = r >> 2;
                int s2 = (r & 3) * GTHREADS + tid;
                int tl = s2 >> 3;
                int c  = s2 & 7;
                pfx[r] = *reinterpret_cast<const float4*>(
                    xn + (size_t)tl * H + 32 * h + c * 4);
            }
            const float* wn = Wm + (kc + 1) * KTILE * E;
#pragma unroll
            for (int r = 0; r < 2; r++)
                pfw[r] = *reinterpret_cast<const float4*>(wn + (r * GTHREADS + tid) * 4);
        }

#pragma unroll
        for (int kk = 0; kk < KTILE; kk++) {
            const float2 xv =
                *reinterpret_cast<const float2*>(xs + kk * XW + 2 * tl2);
            unsigned long long xx0, xx1;
            asm("mov.b64 %0, {%1,%1};" : "=l"(xx0) : "r"(__float_as_uint(xv.x)));
            asm("mov.b64 %0, {%1,%1};" : "=l"(xx1) : "r"(__float_as_uint(xv.y)));
            const ulonglong2* wr =
                reinterpret_cast<const ulonglong2*>(ws + kk * WW + (eh << 3));
            ulonglong2 w0 = wr[0];   // broadcast: warp-uniform address
            ulonglong2 w1 = wr[1];
            asm("fma.rn.f32x2 %0, %1, %2, %0;" : "+l"(acc[0]) : "l"(xx0), "l"(w0.x));
            asm("fma.rn.f32x2 %0, %1, %2, %0;" : "+l"(acc[1]) : "l"(xx0), "l"(w0.y));
            asm("fma.rn.f32x2 %0, %1, %2, %0;" : "+l"(acc[2]) : "l"(xx0), "l"(w1.x));
            asm("fma.rn.f32x2 %0, %1, %2, %0;" : "+l"(acc[3]) : "l"(xx0), "l"(w1.y));
            asm("fma.rn.f32x2 %0, %1, %2, %0;" : "+l"(acc[4]) : "l"(xx1), "l"(w0.x));
            asm("fma.rn.f32x2 %0, %1, %2, %0;" : "+l"(acc[5]) : "l"(xx1), "l"(w0.y));
            asm("fma.rn.f32x2 %0, %1, %2, %0;" : "+l"(acc[6]) : "l"(xx1), "l"(w1.x));
            asm("fma.rn.f32x2 %0, %1, %2, %0;" : "+l"(acc[7]) : "l"(xx1), "l"(w1.y));
        }
    }

    __syncthreads();   // xs/ws dead; psm/zsm overlay

    {
        const int t0 = 2 * tl2, t1 = 2 * tl2 + 1;
#pragma unroll
        for (int i = 0; i < 4; i++) {
            float2 f0 = *reinterpret_cast<float2*>(&acc[i]);
            float2 f1 = *reinterpret_cast<float2*>(&acc[4 + i]);
            psm[t0 * 33 + (eh << 3) + 2*i]     = f0.x;
            psm[t0 * 33 + (eh << 3) + 2*i + 1] = f0.y;
            psm[t1 * 33 + (eh << 3) + 2*i]     = f1.x;
            psm[t1 * 33 + (eh << 3) + 2*i + 1] = f1.y;
        }
    }
    __syncthreads();

    if (eh == 0) {
#pragma unroll
        for (int u = 0; u < 2; u++) {
            const int tk = 2 * tl2 + u;
            float l[E];
#pragma unroll
            for (int e = 0; e < E; e++) l[e] = psm[tk * 33 + e];
#pragma unroll
            for (int e = 0; e < E; e++) l[e] += __ldg(&bv[e]);

            float m = l[0];
#pragma unroll
            for (int e = 1; e < E; e++) m = fmaxf(m, l[e]);
            float s = 0.f;
#pragma unroll
            for (int e = 0; e < E; e++) { l[e] = expf(l[e] - m); s += l[e]; }
            const float inv = 1.f / s;
#pragma unroll
            for (int e = 0; e < E; e++) psm[tk * 33 + e] = l[e] * inv;

            const float lse = m + logf(s);
            zsm[tk] = lse * lse;
        }
    }
    __syncthreads();

#pragma unroll
    for (int r = 0; r < 16; r++) {
        int idx = r * GTHREADS + tid;
        int e = idx >> 7;
        int t = idx & (MTILE - 1);
        g_probs[(size_t)(g * E + e) * T + tt0 + t] = psm[t * 33 + e];
    }

    if (tid == 0) {
        float s = 0.f;
#pragma unroll
        for (int i = 0; i < MTILE; i++) s += zsm[i];
        g_zpart[bid] = s;
    }
}

// ---------------------------------------------------------------------------
// Kernel B: bid<256  = top-64 selection -> z-loss (blk 0) -> staged scatter
//                      (combine after g_done_c, dispatch after g_done_d)
//           bid>=256 = zero combine share -> signal c -> zero dispatch share
//                      -> signal d.
// ---------------------------------------------------------------------------
__global__ __launch_bounds__(NTHREADS)
void router_zero_sel(float* __restrict__ out)
{
    const int bid = blockIdx.x;
    const int tid = threadIdx.x;

    if (bid >= SEL_BLOCKS) {
        uint4 z; z.x = 0u; z.y = 0u; z.z = 0u; z.w = 0u;
        const int zb = bid - SEL_BLOCKS;
        const size_t stride = (size_t)ZERO_BLOCKS * NTHREADS;

        // ---- combine half first ----
        {
            uint4* o4 = reinterpret_cast<uint4*>(out);
            size_t i = (size_t)zb * NTHREADS + tid;
            for (; i < N4H; i += stride) __stcs(o4 + i, z);
        }
        __threadfence();
        __syncthreads();
        if (tid == 0) atomicAdd(&g_done_c, 1u);

        // ---- dispatch half ----
        {
            uint4* o4 = reinterpret_cast<uint4*>(out) + N4H;
            size_t i = (size_t)zb * NTHREADS + tid;
            for (; i < N4H; i += stride) __stcs(o4 + i, z);
        }
        __threadfence();
        __syncthreads();
        if (tid == 0) atomicAdd(&g_done_d, 1u);
        return;
    }

    // ---- selection for (g,e) = bid ----
    const int g = bid >> 5;
    const int e = bid & (E - 1);
    const float* row = g_probs + (size_t)bid * T;

    float v[16];
#pragma unroll
    for (int j = 0; j < 16; j++) v[j] = row[tid + j * NTHREADS];

    float bvv = -INFINITY; int bt = tid;
#pragma unroll
    for (int j = 0; j < 16; j++)
        if (v[j] > bvv) { bvv = v[j]; bt = j * NTHREADS + tid; }

    __shared__ float swv[8];
    __shared__ int   swt[8];
    __shared__ int   wint;
    __shared__ float topv_sh[C];
    __shared__ int   topt_sh[C];

    const int lane = tid & 31;
    const int wrp  = tid >> 5;

    for (int c = 0; c < C; c++) {
        float rv = bvv; int rt = bt;
#pragma unroll
        for (int off = 16; off; off >>= 1) {
            float ov = __shfl_xor_sync(0xffffffffu, rv, off);
            int   oi = __shfl_xor_sync(0xffffffffu, rt, off);
            if (ov > rv || (ov == rv && oi < rt)) { rv = ov; rt = oi; }
        }
        if (lane == 0) { swv[wrp] = rv; swt[wrp] = rt; }
        __syncthreads();
        if (tid == 0) {
            float Rv = swv[0]; int Rt = swt[0];
#pragma unroll
            for (int w = 1; w < 8; w++)
                if (swv[w] > Rv || (swv[w] == Rv && swt[w] < Rt)) {
                    Rv = swv[w]; Rt = swt[w];
                }
            wint = Rt;
            topv_sh[c] = Rv;
            topt_sh[c] = Rt;
        }
        __syncthreads();
        const int wt = wint;
        if ((wt & (NTHREADS - 1)) == tid) {
            v[wt >> 8] = -INFINITY;
            bvv = -INFINITY; bt = tid;
#pragma unroll
            for (int j = 0; j < 16; j++)
                if (v[j] > bvv) { bvv = v[j]; bt = j * NTHREADS + tid; }
        }
    }

    // z-loss: element 2*GTEC is never memset -> write immediately (blk 0)
    if (bid == 0 && tid == 0) {
        float s = 0.f;
        for (int i = 0; i < GEMM_BLOCKS; i++) s += g_zpart[i];
        out[2 * GTEC] = s / (float)GT;
    }

    // precompute this thread's winner offset
    size_t off = 0;
    if (tid < C)
        off = (((size_t)(g * T + topt_sh[tid])) * E + e) * C + tid;

    // ---- combine scatter: wait for combine half only ----
    if (tid == 0) {
        volatile unsigned int* p = &g_done_c;
        while (*p < ZERO_BLOCKS) __nanosleep(128);
    }
    __syncthreads();
    __threadfence();
    if (tid < C) out[off] = topv_sh[tid];

    // ---- dispatch scatter: wait for dispatch half ----
    if (tid == 0) {
        volatile unsigned int* p = &g_done_d;
        while (*p < ZERO_BLOCKS) __nanosleep(128);
    }
    __syncthreads();
    __threadfence();
    if (tid < C) out[GTEC + off] = 1.0f;
}

// ---------------------------------------------------------------------------
extern "C" void kernel_launch(void* const* d_in, const int* in_sizes, int n_in,
                              void* d_out, int out_size)
{
    const float* x  = (const float*)d_in[0];
    const float* Wm = (const float*)d_in[1];
    const float* bv = (const float*)d_in[2];
    float* out = (float*)d_out;

    router_gemm<<<GEMM_BLOCKS, GTHREADS>>>(x, Wm, bv);
    router_zero_sel<<<SEL_BLOCKS + ZERO_BLOCKS, NTHREADS>>>(out);
}